// round 11
// baseline (speedup 1.0000x reference)
#include <cuda_runtime.h>
#include <math.h>

#define Bq   4
#define Nn   192
#define Hh   128
#define NBt  3
#define ROWS (Bq*Nn)       // 768
#define EMAX (ROWS*Nn)
#define TE   32            // edges per tile
#define FST  12            // feature stride (floats)
#define SHS  36            // sh row stride (floats)
#define GRID_E 740

typedef unsigned long long ull;

// ---- scratch (device globals) ----
__device__ __align__(16) float g_F[ROWS*Hh];
__device__ __align__(16) float g_preA[ROWS*Hh];
__device__ __align__(16) float g_preB[ROWS*Hh];
__device__ __align__(16) float g_agg[ROWS*Hh];
__device__ int   g_cnt[ROWS];
__device__ int   g_nE;
__device__ int   g_eI[EMAX];
__device__ int   g_eJ[EMAX];
__device__ __align__(16) float g_feat[(size_t)EMAX*FST];
__device__ __align__(16) ull   g_Wcd[NBt*256*Hh];   // folded weights, duplicated pairs
__device__ __align__(16) float g_cvec[NBt*Hh];

__device__ __forceinline__ float silu_f(float x) { return x / (1.0f + __expf(-x)); }
__device__ __forceinline__ ull fma2(ull a, ull b, ull c) {
    ull d; asm("fma.rn.f32x2 %0, %1, %2, %3;" : "=l"(d) : "l"(a), "l"(b), "l"(c)); return d;
}
__device__ __forceinline__ ull pack2(float lo, float hi) {
    ull d; asm("mov.b64 %0, {%1, %2};" : "=l"(d) : "f"(lo), "f"(hi)); return d;
}
__device__ __forceinline__ void unpack2(ull v, float& lo, float& hi) {
    asm("mov.b64 {%0, %1}, %2;" : "=f"(lo), "=f"(hi) : "l"(v));
}

// feats = emb[idx]; preA/preB block 0; zero agg/out; reset edge counter
__global__ void k_init(const int* __restrict__ idx, const float* __restrict__ emb,
                       const float* __restrict__ ew1, float* __restrict__ out) {
    int row = blockIdx.x, h = threadIdx.x;
    __shared__ float f[Hh];
    float v = emb[idx[row]*Hh + h];
    g_F[row*Hh + h] = v;
    f[h] = v;
    if (row == 0 && h < Bq) out[h] = 0.f;
    if (row == 0 && h == 0) g_nE = 0;
    __syncthreads();
    const float* W1a = ew1;
    const float* W1b = ew1 + Hh*Hh;
    float a = 0.f, bv = 0.f;
    #pragma unroll 8
    for (int k = 0; k < Hh; k++) {
        float fk = f[k];
        a  += fk * W1a[k*Hh + h];
        bv += fk * W1b[k*Hh + h];
    }
    g_preA[row*Hh + h] = a;
    g_preB[row*Hh + h] = bv;
    g_agg[row*Hh + h] = 0.f;
}

// flat edge list + block-invariant geometry features
__global__ void k_edges(const float* __restrict__ pos, const int* __restrict__ adj,
                        const float* __restrict__ mask,
                        const float* __restrict__ dpw, const float* __restrict__ dpb) {
    int row = blockIdx.x;
    int b = row / Nn, i = row % Nn;
    int j = threadIdx.x;
    __shared__ int s_cnt, s_base;
    if (j == 0) s_cnt = 0;
    __syncthreads();

    const float* pb = pos + (size_t)b*Nn*3;
    float xi = pb[i*3+0], yi = pb[i*3+1], zi = pb[i*3+2];
    float xj = pb[j*3+0], yj = pb[j*3+1], zj = pb[j*3+2];
    float dx = xi-xj, dy = yi-yj, dz = zi-zj;
    float dist = sqrtf(dx*dx + dy*dy + dz*dz);
    bool valid = (mask[row] > 0.f) && (mask[b*Nn + j] > 0.f) && (dist <= 5.0f)
                 && (adj[(size_t)b*Nn*Nn + (size_t)i*Nn + j] > 0) && (i != j);
    int el = -1;
    float ft[10];
    if (valid) {
        el = atomicAdd(&s_cnt, 1);
        float inv = 1.0f / (dist + 1e-8f);
        float ux = dx*inv, uy = dy*inv, uz = dz*inv;
        const float w = (5.0f/6.0f) + 1e-8f;
        #pragma unroll
        for (int r = 0; r < 6; r++) {
            float t = (dist - (float)r) / w;
            ft[r] = expf(-0.5f * t * t);
        }
        #pragma unroll
        for (int s = 0; s < 4; s++) {
            float vv = ux*dpw[0*4+s] + uy*dpw[1*4+s] + uz*dpw[2*4+s] + dpb[s];
            ft[6+s] = tanhf(vv);
        }
    }
    __syncthreads();
    if (j == 0) {
        g_cnt[row] = s_cnt;
        s_base = atomicAdd(&g_nE, s_cnt);
    }
    __syncthreads();
    if (valid) {
        int e = s_base + el;
        g_eI[e] = row;
        g_eJ[e] = b*Nn + j;
        float4* fo = (float4*)&g_feat[(size_t)e*FST];
        fo[0] = make_float4(ft[0], ft[1], ft[2], ft[3]);
        fo[1] = make_float4(ft[4], ft[5], ft[6], ft[7]);
        fo[2] = make_float4(ft[8], ft[9], 0.f, 0.f);
    }
}

// all 3 blocks' weight folding -> duplicated-pair layout
__global__ void k_fold(const float* __restrict__ rw2, const float* __restrict__ rb2,
                       const float* __restrict__ dw2, const float* __restrict__ db2,
                       const float* __restrict__ ew1, const float* __restrict__ eb1) {
    int h = threadIdx.x;
    int t  = blockIdx.x / 257;
    int kk = blockIdx.x % 257;
    const float* W1c = ew1 + (size_t)t*4*Hh*Hh + 2*Hh*Hh;
    const float* W1d = ew1 + (size_t)t*4*Hh*Hh + 3*Hh*Hh;
    if (kk < 256) {
        const float* src = (kk < 128) ? (rw2 + (size_t)t*Hh*Hh + kk*Hh)
                                      : (dw2 + (size_t)t*Hh*Hh + (kk-128)*Hh);
        const float* W   = (kk < 128) ? W1c : W1d;
        __shared__ float srow[Hh];
        srow[h] = src[h];
        __syncthreads();
        float s = 0.f;
        #pragma unroll 8
        for (int m = 0; m < Hh; m++) s += srow[m] * W[m*Hh + h];
        g_Wcd[(size_t)(t*256 + kk)*Hh + h] = pack2(s, s);
    } else {
        __shared__ float rb[Hh], db[Hh];
        rb[h] = rb2[t*Hh + h];
        db[h] = db2[t*Hh + h];
        __syncthreads();
        float s = eb1[t*Hh + h];
        #pragma unroll 8
        for (int m = 0; m < Hh; m++) s += rb[m]*W1c[m*Hh + h] + db[m]*W1d[m*Hh + h];
        g_cvec[t*Hh + h] = s;
    }
}

// Edge MLP + aggregation: 32-edge tiles, WH=4, pre-duplicated weights (no packs, MLP 8)
__global__ void __launch_bounds__(Hh, 5)
k_edge_mlp(const float* __restrict__ rw1, const float* __restrict__ rb1,
           const float* __restrict__ dw1, const float* __restrict__ db1, int t) {
    __shared__ __align__(16) float sh[256*SHS];
    __shared__ int s_eI[TE], s_eJ[TE];
    int tid  = threadIdx.x;
    int hq   = tid & 31;
    int grp  = tid >> 5;
    int eoff = grp * 8;

    int nE = g_nE;
    int nT = (nE + TE - 1) / TE;
    const ull* Wcd = g_Wcd + (size_t)t*256*Hh;
    float4 cv = *(const float4*)&g_cvec[t*Hh + 4*hq];

    for (int tile = blockIdx.x; tile < nT; tile += gridDim.x) {
        int e0 = tile * TE;
        int ne = min(TE, nE - e0);
        __syncthreads();
        if (tid < TE) {
            int idx = (tid < ne) ? (e0 + tid) : e0;
            s_eI[tid] = g_eI[idx];
            s_eJ[tid] = g_eJ[idx];
        }
        {
            float rb1h = rb1[t*Hh + tid], db1h = db1[t*Hh + tid];
            float rw[6], dwv[4];
            #pragma unroll
            for (int r = 0; r < 6; r++) rw[r] = rw1[(t*6 + r)*Hh + tid];
            #pragma unroll
            for (int r = 0; r < 4; r++) dwv[r] = dw1[(t*4 + r)*Hh + tid];
            #pragma unroll
            for (int q = 0; q < 4; q++) {
                float va[8], vb[8];
                #pragma unroll
                for (int e = 0; e < 8; e++) {
                    int ge = q*8 + e;
                    if (ge < ne) {
                        const float4* fp = (const float4*)&g_feat[(size_t)(e0+ge)*FST];
                        float4 fa = fp[0], fb4 = fp[1], fc = fp[2];
                        float a = rb1h + fa.x*rw[0] + fa.y*rw[1] + fa.z*rw[2]
                                       + fa.w*rw[3] + fb4.x*rw[4] + fb4.y*rw[5];
                        float bb = db1h + fb4.z*dwv[0] + fb4.w*dwv[1]
                                        + fc.x*dwv[2] + fc.y*dwv[3];
                        va[e] = silu_f(a);
                        vb[e] = silu_f(bb);
                    } else { va[e] = 0.f; vb[e] = 0.f; }
                }
                float4* rowA = (float4*)&sh[tid*SHS + q*8];
                float4* rowB = (float4*)&sh[(128+tid)*SHS + q*8];
                rowA[0] = make_float4(va[0], va[1], va[2], va[3]);
                rowA[1] = make_float4(va[4], va[5], va[6], va[7]);
                rowB[0] = make_float4(vb[0], vb[1], vb[2], vb[3]);
                rowB[1] = make_float4(vb[4], vb[5], vb[6], vb[7]);
            }
        }
        __syncthreads();

        ull acc[4][4];
        #pragma unroll
        for (int p = 0; p < 4; p++) {
            int ea = eoff + 2*p, eb = ea + 1;
            float4 a0 = *(const float4*)&g_preA[s_eI[ea]*Hh + 4*hq];
            float4 b0 = *(const float4*)&g_preB[s_eJ[ea]*Hh + 4*hq];
            float4 a1 = *(const float4*)&g_preA[s_eI[eb]*Hh + 4*hq];
            float4 b1 = *(const float4*)&g_preB[s_eJ[eb]*Hh + 4*hq];
            acc[0][p] = pack2(a0.x + b0.x + cv.x, a1.x + b1.x + cv.x);
            acc[1][p] = pack2(a0.y + b0.y + cv.y, a1.y + b1.y + cv.y);
            acc[2][p] = pack2(a0.z + b0.z + cv.z, a1.z + b1.z + cv.z);
            acc[3][p] = pack2(a0.w + b0.w + cv.w, a1.w + b1.w + cv.w);
        }

        #pragma unroll 4
        for (int k = 0; k < 256; k++) {
            const ull* wr = Wcd + ((size_t)k << 7) + 4*hq;
            ulonglong2 wA = __ldg((const ulonglong2*)wr);        // (w0,w0),(w1,w1)
            ulonglong2 wB = __ldg((const ulonglong2*)(wr + 2));  // (w2,w2),(w3,w3)
            const float* row = &sh[k*SHS + eoff];
            ulonglong2 sA = *(const ulonglong2*)(row);
            ulonglong2 sB = *(const ulonglong2*)(row + 4);
            acc[0][0]=fma2(sA.x,wA.x,acc[0][0]); acc[0][1]=fma2(sA.y,wA.x,acc[0][1]);
            acc[0][2]=fma2(sB.x,wA.x,acc[0][2]); acc[0][3]=fma2(sB.y,wA.x,acc[0][3]);
            acc[1][0]=fma2(sA.x,wA.y,acc[1][0]); acc[1][1]=fma2(sA.y,wA.y,acc[1][1]);
            acc[1][2]=fma2(sB.x,wA.y,acc[1][2]); acc[1][3]=fma2(sB.y,wA.y,acc[1][3]);
            acc[2][0]=fma2(sA.x,wB.x,acc[2][0]); acc[2][1]=fma2(sA.y,wB.x,acc[2][1]);
            acc[2][2]=fma2(sB.x,wB.x,acc[2][2]); acc[2][3]=fma2(sB.y,wB.x,acc[2][3]);
            acc[3][0]=fma2(sA.x,wB.y,acc[3][0]); acc[3][1]=fma2(sA.y,wB.y,acc[3][1]);
            acc[3][2]=fma2(sB.x,wB.y,acc[3][2]); acc[3][3]=fma2(sB.y,wB.y,acc[3][3]);
        }

        int neH = ne - eoff; neH = neH < 0 ? 0 : (neH > 8 ? 8 : neH);
        #pragma unroll
        for (int c = 0; c < 4; c++) {
            float mv[8];
            #pragma unroll
            for (int p = 0; p < 4; p++) {
                float lo, hi;
                unpack2(acc[c][p], lo, hi);
                mv[2*p] = silu_f(lo); mv[2*p+1] = silu_f(hi);
            }
            int hh = 4*hq + c;
            int cur = -1; float s = 0.f;
            #pragma unroll
            for (int e = 0; e < 8; e++) {
                if (e < neH) {
                    int i = s_eI[eoff + e];
                    if (i != cur) {
                        if (cur >= 0) atomicAdd(&g_agg[cur*Hh + hh], s);
                        cur = i; s = mv[e];
                    } else s += mv[e];
                }
            }
            if (cur >= 0) atomicAdd(&g_agg[cur*Hh + hh], s);
        }
    }
}

// node update (+ next-block pre, or output head on last block)
__global__ void k_node(const float* __restrict__ ew2, const float* __restrict__ eb2,
                       const float* __restrict__ nw1, const float* __restrict__ nb1,
                       const float* __restrict__ nw2, const float* __restrict__ nb2,
                       const float* __restrict__ ew1,
                       const float* __restrict__ ow1, const float* __restrict__ ob1,
                       const float* __restrict__ ow2, const float* __restrict__ ob2,
                       const float* __restrict__ mask, float* __restrict__ out, int t) {
    int row = blockIdx.x, h = threadIdx.x;
    __shared__ float x[256];
    __shared__ float agg_s[Hh];
    __shared__ float u[Hh];
    __shared__ float red[4];
    float fh = g_F[row*Hh + h];
    x[h] = fh;
    agg_s[h] = g_agg[row*Hh + h];
    __syncthreads();
    const float* EW2 = ew2 + (size_t)t*Hh*Hh;
    float deg = (float)g_cnt[row];
    float s = deg * eb2[t*Hh + h];
    #pragma unroll 8
    for (int k = 0; k < Hh; k++) s += agg_s[k] * EW2[k*Hh + h];
    x[128 + h] = s;
    __syncthreads();
    const float* NW1 = nw1 + (size_t)t*256*Hh;
    float uacc = nb1[t*Hh + h];
    #pragma unroll 8
    for (int k = 0; k < 256; k++) uacc += x[k] * NW1[k*Hh + h];
    u[h] = silu_f(uacc);
    __syncthreads();
    const float* NW2 = nw2 + (size_t)t*Hh*Hh;
    float upd = nb2[t*Hh + h];
    #pragma unroll 8
    for (int k = 0; k < Hh; k++) upd += u[k] * NW2[k*Hh + h];
    float newf = fh + upd;
    g_F[row*Hh + h] = newf;

    __syncthreads();
    x[h] = newf;
    __syncthreads();
    if (t + 1 < NBt) {
        const float* W1a = ew1 + (size_t)(t+1)*4*Hh*Hh;
        const float* W1b = W1a + Hh*Hh;
        float a = 0.f, bv = 0.f;
        #pragma unroll 8
        for (int k = 0; k < Hh; k++) {
            float fk = x[k];
            a  += fk * W1a[k*Hh + h];
            bv += fk * W1b[k*Hh + h];
        }
        g_preA[row*Hh + h] = a;
        g_preB[row*Hh + h] = bv;
        g_agg[row*Hh + h] = 0.f;
    } else {
        float oacc = ob1[h];
        #pragma unroll 8
        for (int k = 0; k < Hh; k++) oacc += x[k] * ow1[k*Hh + h];
        float val = silu_f(oacc) * ow2[h];
        #pragma unroll
        for (int off = 16; off > 0; off >>= 1)
            val += __shfl_down_sync(0xffffffffu, val, off);
        if ((h & 31) == 0) red[h >> 5] = val;
        __syncthreads();
        if (h == 0) {
            float v = red[0] + red[1] + red[2] + red[3] + ob2[0];
            v *= mask[row];
            atomicAdd(&out[row / Nn], v);
        }
    }
}

extern "C" void kernel_launch(void* const* d_in, const int* in_sizes, int n_in,
                              void* d_out, int out_size) {
    const int*   node_indices = (const int*)  d_in[0];
    const float* positions    = (const float*)d_in[1];
    const int*   adjacency    = (const int*)  d_in[2];
    const float* mask         = (const float*)d_in[3];
    const float* emb          = (const float*)d_in[4];
    const float* dpw          = (const float*)d_in[5];
    const float* dpb          = (const float*)d_in[6];
    const float* rbf_w1 = (const float*)d_in[7];
    const float* rbf_b1 = (const float*)d_in[8];
    const float* rbf_w2 = (const float*)d_in[9];
    const float* rbf_b2 = (const float*)d_in[10];
    const float* dir_w1 = (const float*)d_in[11];
    const float* dir_b1 = (const float*)d_in[12];
    const float* dir_w2 = (const float*)d_in[13];
    const float* dir_b2 = (const float*)d_in[14];
    const float* edge_w1 = (const float*)d_in[15];
    const float* edge_b1 = (const float*)d_in[16];
    const float* edge_w2 = (const float*)d_in[17];
    const float* edge_b2 = (const float*)d_in[18];
    const float* node_w1 = (const float*)d_in[19];
    const float* node_b1 = (const float*)d_in[20];
    const float* node_w2 = (const float*)d_in[21];
    const float* node_b2 = (const float*)d_in[22];
    const float* ow1 = (const float*)d_in[23];
    const float* ob1 = (const float*)d_in[24];
    const float* ow2 = (const float*)d_in[25];
    const float* ob2 = (const float*)d_in[26];
    float* out = (float*)d_out;

    k_init<<<ROWS, Hh>>>(node_indices, emb, edge_w1, out);      // resets g_nE
    k_edges<<<ROWS, Nn>>>(positions, adjacency, mask, dpw, dpb);
    k_fold<<<3*257, Hh>>>(rbf_w2, rbf_b2, dir_w2, dir_b2, edge_w1, edge_b1);
    for (int t = 0; t < NBt; t++) {
        k_edge_mlp<<<GRID_E, Hh>>>(rbf_w1, rbf_b1, dir_w1, dir_b1, t);
        k_node<<<ROWS, Hh>>>(edge_w2, edge_b2, node_w1, node_b1, node_w2, node_b2,
                             edge_w1, ow1, ob1, ow2, ob2, mask, out, t);
    }
}

// round 12
// speedup vs baseline: 1.4078x; 1.4078x over previous
#include <cuda_runtime.h>
#include <math.h>

#define Bq   4
#define Nn   192
#define Hh   128
#define NBt  3
#define ROWS (Bq*Nn)       // 768
#define EMAX (ROWS*Nn)
#define TE   32            // edges per tile
#define FST  12            // feature stride (floats)
#define SHS  36            // sh row stride (floats)
#define GRID_E 740
#define RN   4             // rows per CTA, node-side

typedef unsigned long long ull;

// ---- scratch (device globals) ----
__device__ __align__(16) float g_F[ROWS*Hh];
__device__ __align__(16) float g_preA[ROWS*Hh];
__device__ __align__(16) float g_preB[ROWS*Hh];
__device__ __align__(16) float g_agg[ROWS*Hh];
__device__ int   g_cnt[ROWS];
__device__ int   g_nE;
__device__ int   g_eI[EMAX];
__device__ int   g_eJ[EMAX];
__device__ __align__(16) float g_feat[(size_t)EMAX*FST];
__device__ __align__(16) float g_Wc[NBt*256*Hh];   // folded [RW;DW], k-major rows of 128
__device__ __align__(16) float g_cvec[NBt*Hh];

__device__ __forceinline__ float silu_f(float x) { return x / (1.0f + __expf(-x)); }
__device__ __forceinline__ ull fma2(ull a, ull b, ull c) {
    ull d; asm("fma.rn.f32x2 %0, %1, %2, %3;" : "=l"(d) : "l"(a), "l"(b), "l"(c)); return d;
}
__device__ __forceinline__ ull pack2(float lo, float hi) {
    ull d; asm("mov.b64 %0, {%1, %2};" : "=l"(d) : "f"(lo), "f"(hi)); return d;
}
__device__ __forceinline__ void unpack2(ull v, float& lo, float& hi) {
    asm("mov.b64 {%0, %1}, %2;" : "=f"(lo), "=f"(hi) : "l"(v));
}

// feats = emb[idx]; preA/preB block 0. RN=4 rows/CTA, 256 thr (kh=0:W1a, kh=1:W1b)
__global__ void k_init(const int* __restrict__ idx, const float* __restrict__ emb,
                       const float* __restrict__ ew1, float* __restrict__ out) {
    int tid = threadIdx.x;
    int h = tid & 127, kh = tid >> 7;
    int r0 = blockIdx.x * RN;
    __shared__ __align__(16) float xs[RN][Hh];
    for (int r = kh*2; r < kh*2+2; r++) {
        float v = emb[idx[r0+r]*Hh + h];
        g_F[(r0+r)*Hh + h] = v;
        xs[r][h] = v;
        g_agg[(r0+r)*Hh + h] = 0.f;
    }
    if (blockIdx.x == 0 && tid < Bq) out[tid] = 0.f;
    if (blockIdx.x == 0 && tid == 0) g_nE = 0;
    __syncthreads();
    const float* W = ew1 + (size_t)kh*Hh*Hh;    // kh=0: W1a, kh=1: W1b (block 0)
    float a[RN] = {0.f, 0.f, 0.f, 0.f};
    for (int k = 0; k < Hh; k += 4) {
        float w0 = W[(k+0)*Hh+h], w1 = W[(k+1)*Hh+h];
        float w2 = W[(k+2)*Hh+h], w3 = W[(k+3)*Hh+h];
        #pragma unroll
        for (int r = 0; r < RN; r++) {
            float4 x = *(const float4*)&xs[r][k];
            a[r] += x.x*w0 + x.y*w1 + x.z*w2 + x.w*w3;
        }
    }
    float* dst = kh ? g_preB : g_preA;
    #pragma unroll
    for (int r = 0; r < RN; r++) dst[(r0+r)*Hh + h] = a[r];
}

// flat edge list + block-invariant geometry features (unchanged)
__global__ void k_edges(const float* __restrict__ pos, const int* __restrict__ adj,
                        const float* __restrict__ mask,
                        const float* __restrict__ dpw, const float* __restrict__ dpb) {
    int row = blockIdx.x;
    int b = row / Nn, i = row % Nn;
    int j = threadIdx.x;
    __shared__ int s_cnt, s_base;
    if (j == 0) s_cnt = 0;
    __syncthreads();

    const float* pb = pos + (size_t)b*Nn*3;
    float xi = pb[i*3+0], yi = pb[i*3+1], zi = pb[i*3+2];
    float xj = pb[j*3+0], yj = pb[j*3+1], zj = pb[j*3+2];
    float dx = xi-xj, dy = yi-yj, dz = zi-zj;
    float dist = sqrtf(dx*dx + dy*dy + dz*dz);
    bool valid = (mask[row] > 0.f) && (mask[b*Nn + j] > 0.f) && (dist <= 5.0f)
                 && (adj[(size_t)b*Nn*Nn + (size_t)i*Nn + j] > 0) && (i != j);
    int el = -1;
    float ft[10];
    if (valid) {
        el = atomicAdd(&s_cnt, 1);
        float inv = 1.0f / (dist + 1e-8f);
        float ux = dx*inv, uy = dy*inv, uz = dz*inv;
        const float w = (5.0f/6.0f) + 1e-8f;
        #pragma unroll
        for (int r = 0; r < 6; r++) {
            float t = (dist - (float)r) / w;
            ft[r] = expf(-0.5f * t * t);
        }
        #pragma unroll
        for (int s = 0; s < 4; s++) {
            float vv = ux*dpw[0*4+s] + uy*dpw[1*4+s] + uz*dpw[2*4+s] + dpb[s];
            ft[6+s] = tanhf(vv);
        }
    }
    __syncthreads();
    if (j == 0) {
        g_cnt[row] = s_cnt;
        s_base = atomicAdd(&g_nE, s_cnt);
    }
    __syncthreads();
    if (valid) {
        int e = s_base + el;
        g_eI[e] = row;
        g_eJ[e] = b*Nn + j;
        float4* fo = (float4*)&g_feat[(size_t)e*FST];
        fo[0] = make_float4(ft[0], ft[1], ft[2], ft[3]);
        fo[1] = make_float4(ft[4], ft[5], ft[6], ft[7]);
        fo[2] = make_float4(ft[8], ft[9], 0.f, 0.f);
    }
}

// weight folding: 4 kk-rows/CTA share one W read; 256 thr with kh-split m-chain
__global__ void k_fold(const float* __restrict__ rw2, const float* __restrict__ rb2,
                       const float* __restrict__ dw2, const float* __restrict__ db2,
                       const float* __restrict__ ew1, const float* __restrict__ eb1) {
    int tid = threadIdx.x;
    int h = tid & 127, kh = tid >> 7;
    int t   = blockIdx.x / 65;
    int sub = blockIdx.x % 65;
    const float* W1c = ew1 + (size_t)t*4*Hh*Hh + 2*Hh*Hh;
    const float* W1d = W1c + Hh*Hh;
    __shared__ __align__(16) float srow[RN][Hh];
    __shared__ float part[2][RN][Hh];
    if (sub < 64) {
        int kk0 = sub * RN;                     // 4-aligned; never straddles 128
        const float* W = (kk0 < 128) ? W1c : W1d;
        for (int r = kh*2; r < kh*2+2; r++) {
            int kk = kk0 + r;
            const float* src = (kk < 128) ? (rw2 + ((size_t)t*128 + kk)*Hh)
                                          : (dw2 + ((size_t)t*128 + kk - 128)*Hh);
            srow[r][h] = src[h];
        }
        __syncthreads();
        float acc[RN] = {0.f, 0.f, 0.f, 0.f};
        for (int m = kh*64; m < kh*64+64; m += 4) {
            float w0 = W[(m+0)*Hh+h], w1 = W[(m+1)*Hh+h];
            float w2 = W[(m+2)*Hh+h], w3 = W[(m+3)*Hh+h];
            #pragma unroll
            for (int r = 0; r < RN; r++) {
                float4 x = *(const float4*)&srow[r][m];
                acc[r] += x.x*w0 + x.y*w1 + x.z*w2 + x.w*w3;
            }
        }
        #pragma unroll
        for (int r = 0; r < RN; r++) part[kh][r][h] = acc[r];
        __syncthreads();
        if (kh == 0) {
            #pragma unroll
            for (int r = 0; r < RN; r++)
                g_Wc[(size_t)(t*256 + kk0 + r)*Hh + h] = part[0][r][h] + part[1][r][h];
        }
    } else {
        __shared__ float rb[Hh], db[Hh];
        if (kh == 0) rb[h] = rb2[t*Hh + h];
        else         db[h] = db2[t*Hh + h];
        __syncthreads();
        float s = 0.f;
        for (int m = kh*64; m < kh*64+64; m++)
            s += rb[m]*W1c[m*Hh + h] + db[m]*W1d[m*Hh + h];
        part[kh][0][h] = s;
        __syncthreads();
        if (kh == 0) g_cvec[t*Hh + h] = eb1[t*Hh + h] + part[0][0][h] + part[1][0][h];
    }
}

// Edge MLP + aggregation — EXACT R8 kernel (proven 59.7us)
__global__ void __launch_bounds__(Hh, 5)
k_edge_mlp(const float* __restrict__ rw1, const float* __restrict__ rb1,
           const float* __restrict__ dw1, const float* __restrict__ db1, int t) {
    __shared__ __align__(16) float sh[256*SHS];
    __shared__ int s_eI[TE], s_eJ[TE];
    int tid  = threadIdx.x;
    int hq   = tid & 31;
    int grp  = tid >> 5;
    int eoff = grp * 8;

    int nE = g_nE;
    int nT = (nE + TE - 1) / TE;
    const float* Wc = g_Wc + (size_t)t*256*Hh;
    float4 cv = *(const float4*)&g_cvec[t*Hh + 4*hq];

    for (int tile = blockIdx.x; tile < nT; tile += gridDim.x) {
        int e0 = tile * TE;
        int ne = min(TE, nE - e0);
        __syncthreads();
        if (tid < TE) {
            int idx = (tid < ne) ? (e0 + tid) : e0;
            s_eI[tid] = g_eI[idx];
            s_eJ[tid] = g_eJ[idx];
        }
        {
            float rb1h = rb1[t*Hh + tid], db1h = db1[t*Hh + tid];
            float rw[6], dwv[4];
            #pragma unroll
            for (int r = 0; r < 6; r++) rw[r] = rw1[(t*6 + r)*Hh + tid];
            #pragma unroll
            for (int r = 0; r < 4; r++) dwv[r] = dw1[(t*4 + r)*Hh + tid];
            #pragma unroll
            for (int q = 0; q < 4; q++) {
                float va[8], vb[8];
                #pragma unroll
                for (int e = 0; e < 8; e++) {
                    int ge = q*8 + e;
                    if (ge < ne) {
                        const float4* fp = (const float4*)&g_feat[(size_t)(e0+ge)*FST];
                        float4 fa = fp[0], fb4 = fp[1], fc = fp[2];
                        float a = rb1h + fa.x*rw[0] + fa.y*rw[1] + fa.z*rw[2]
                                       + fa.w*rw[3] + fb4.x*rw[4] + fb4.y*rw[5];
                        float bb = db1h + fb4.z*dwv[0] + fb4.w*dwv[1]
                                        + fc.x*dwv[2] + fc.y*dwv[3];
                        va[e] = silu_f(a);
                        vb[e] = silu_f(bb);
                    } else { va[e] = 0.f; vb[e] = 0.f; }
                }
                float4* rowA = (float4*)&sh[tid*SHS + q*8];
                float4* rowB = (float4*)&sh[(128+tid)*SHS + q*8];
                rowA[0] = make_float4(va[0], va[1], va[2], va[3]);
                rowA[1] = make_float4(va[4], va[5], va[6], va[7]);
                rowB[0] = make_float4(vb[0], vb[1], vb[2], vb[3]);
                rowB[1] = make_float4(vb[4], vb[5], vb[6], vb[7]);
            }
        }
        __syncthreads();

        ull acc[4][4];
        #pragma unroll
        for (int p = 0; p < 4; p++) {
            int ea = eoff + 2*p, eb = ea + 1;
            float4 a0 = *(const float4*)&g_preA[s_eI[ea]*Hh + 4*hq];
            float4 b0 = *(const float4*)&g_preB[s_eJ[ea]*Hh + 4*hq];
            float4 a1 = *(const float4*)&g_preA[s_eI[eb]*Hh + 4*hq];
            float4 b1 = *(const float4*)&g_preB[s_eJ[eb]*Hh + 4*hq];
            acc[0][p] = pack2(a0.x + b0.x + cv.x, a1.x + b1.x + cv.x);
            acc[1][p] = pack2(a0.y + b0.y + cv.y, a1.y + b1.y + cv.y);
            acc[2][p] = pack2(a0.z + b0.z + cv.z, a1.z + b1.z + cv.z);
            acc[3][p] = pack2(a0.w + b0.w + cv.w, a1.w + b1.w + cv.w);
        }

        #pragma unroll 4
        for (int k = 0; k < 256; k++) {
            float4 w = __ldg((const float4*)&Wc[k*Hh + 4*hq]);
            ull w0 = pack2(w.x, w.x), w1 = pack2(w.y, w.y);
            ull w2 = pack2(w.z, w.z), w3 = pack2(w.w, w.w);
            const float* row = &sh[k*SHS + eoff];
            ulonglong2 sA = *(const ulonglong2*)(row);
            ulonglong2 sB = *(const ulonglong2*)(row + 4);
            acc[0][0]=fma2(sA.x,w0,acc[0][0]); acc[0][1]=fma2(sA.y,w0,acc[0][1]);
            acc[0][2]=fma2(sB.x,w0,acc[0][2]); acc[0][3]=fma2(sB.y,w0,acc[0][3]);
            acc[1][0]=fma2(sA.x,w1,acc[1][0]); acc[1][1]=fma2(sA.y,w1,acc[1][1]);
            acc[1][2]=fma2(sB.x,w1,acc[1][2]); acc[1][3]=fma2(sB.y,w1,acc[1][3]);
            acc[2][0]=fma2(sA.x,w2,acc[2][0]); acc[2][1]=fma2(sA.y,w2,acc[2][1]);
            acc[2][2]=fma2(sB.x,w2,acc[2][2]); acc[2][3]=fma2(sB.y,w2,acc[2][3]);
            acc[3][0]=fma2(sA.x,w3,acc[3][0]); acc[3][1]=fma2(sA.y,w3,acc[3][1]);
            acc[3][2]=fma2(sB.x,w3,acc[3][2]); acc[3][3]=fma2(sB.y,w3,acc[3][3]);
        }

        int neH = ne - eoff; neH = neH < 0 ? 0 : (neH > 8 ? 8 : neH);
        #pragma unroll
        for (int c = 0; c < 4; c++) {
            float mv[8];
            #pragma unroll
            for (int p = 0; p < 4; p++) {
                float lo, hi;
                unpack2(acc[c][p], lo, hi);
                mv[2*p] = silu_f(lo); mv[2*p+1] = silu_f(hi);
            }
            int hh = 4*hq + c;
            int cur = -1; float s = 0.f;
            #pragma unroll
            for (int e = 0; e < 8; e++) {
                if (e < neH) {
                    int i = s_eI[eoff + e];
                    if (i != cur) {
                        if (cur >= 0) atomicAdd(&g_agg[cur*Hh + hh], s);
                        cur = i; s = mv[e];
                    } else s += mv[e];
                }
            }
            if (cur >= 0) atomicAdd(&g_agg[cur*Hh + hh], s);
        }
    }
}

// node update: RN=4 rows/CTA, 256 thr, kh splits every k-chain; weight traffic /4
__global__ void k_node(const float* __restrict__ ew2, const float* __restrict__ eb2,
                       const float* __restrict__ nw1, const float* __restrict__ nb1,
                       const float* __restrict__ nw2, const float* __restrict__ nb2,
                       const float* __restrict__ ew1,
                       const float* __restrict__ ow1, const float* __restrict__ ob1,
                       const float* __restrict__ ow2, const float* __restrict__ ob2,
                       const float* __restrict__ mask, float* __restrict__ out, int t) {
    int tid = threadIdx.x;
    int h = tid & 127, kh = tid >> 7;
    int r0 = blockIdx.x * RN;
    __shared__ __align__(16) float xs[RN][256];
    __shared__ __align__(16) float aggs[RN][Hh];
    __shared__ __align__(16) float us[RN][Hh];
    __shared__ float part[2][RN][Hh];
    __shared__ float red[RN][4];

    for (int r = kh*2; r < kh*2+2; r++) {
        xs[r][h]   = g_F[(r0+r)*Hh + h];
        aggs[r][h] = g_agg[(r0+r)*Hh + h];
    }
    __syncthreads();

    // stage 1: aggOut = agg@ew2 + deg*eb2 (k split by kh)
    const float* EW2 = ew2 + (size_t)t*Hh*Hh;
    {
        float s[RN] = {0.f, 0.f, 0.f, 0.f};
        for (int k = kh*64; k < kh*64+64; k += 4) {
            float w0 = EW2[(k+0)*Hh+h], w1 = EW2[(k+1)*Hh+h];
            float w2 = EW2[(k+2)*Hh+h], w3 = EW2[(k+3)*Hh+h];
            #pragma unroll
            for (int r = 0; r < RN; r++) {
                float4 a = *(const float4*)&aggs[r][k];
                s[r] += a.x*w0 + a.y*w1 + a.z*w2 + a.w*w3;
            }
        }
        #pragma unroll
        for (int r = 0; r < RN; r++) part[kh][r][h] = s[r];
    }
    __syncthreads();
    if (kh == 0) {
        float e2 = eb2[t*Hh + h];
        #pragma unroll
        for (int r = 0; r < RN; r++)
            xs[r][Hh + h] = part[0][r][h] + part[1][r][h] + (float)g_cnt[r0+r] * e2;
    }
    __syncthreads();

    // stage 2: u = silu([f, aggOut] @ nw1 + nb1) (k split: 128 each)
    const float* NW1 = nw1 + (size_t)t*256*Hh;
    {
        float u[RN] = {0.f, 0.f, 0.f, 0.f};
        for (int k = kh*128; k < kh*128+128; k += 4) {
            float w0 = NW1[(k+0)*Hh+h], w1 = NW1[(k+1)*Hh+h];
            float w2 = NW1[(k+2)*Hh+h], w3 = NW1[(k+3)*Hh+h];
            #pragma unroll
            for (int r = 0; r < RN; r++) {
                float4 x = *(const float4*)&xs[r][k];
                u[r] += x.x*w0 + x.y*w1 + x.z*w2 + x.w*w3;
            }
        }
        #pragma unroll
        for (int r = 0; r < RN; r++) part[kh][r][h] = u[r];
    }
    __syncthreads();
    if (kh == 0) {
        float b1 = nb1[t*Hh + h];
        #pragma unroll
        for (int r = 0; r < RN; r++)
            us[r][h] = silu_f(part[0][r][h] + part[1][r][h] + b1);
    }
    __syncthreads();

    // stage 3: f += u @ nw2 + nb2
    const float* NW2 = nw2 + (size_t)t*Hh*Hh;
    {
        float upd[RN] = {0.f, 0.f, 0.f, 0.f};
        for (int k = kh*64; k < kh*64+64; k += 4) {
            float w0 = NW2[(k+0)*Hh+h], w1 = NW2[(k+1)*Hh+h];
            float w2 = NW2[(k+2)*Hh+h], w3 = NW2[(k+3)*Hh+h];
            #pragma unroll
            for (int r = 0; r < RN; r++) {
                float4 x = *(const float4*)&us[r][k];
                upd[r] += x.x*w0 + x.y*w1 + x.z*w2 + x.w*w3;
            }
        }
        #pragma unroll
        for (int r = 0; r < RN; r++) part[kh][r][h] = upd[r];
    }
    __syncthreads();
    if (kh == 0) {
        float b2v = nb2[t*Hh + h];
        #pragma unroll
        for (int r = 0; r < RN; r++) {
            float newf = xs[r][h] + part[0][r][h] + part[1][r][h] + b2v;
            g_F[(r0+r)*Hh + h] = newf;
            xs[r][h] = newf;
        }
    }
    __syncthreads();

    if (t + 1 < NBt) {
        // preA/preB for next block: kh=0 -> W1a, kh=1 -> W1b (full chain each)
        const float* W = ew1 + (size_t)(t+1)*4*Hh*Hh + (size_t)kh*Hh*Hh;
        float a[RN] = {0.f, 0.f, 0.f, 0.f};
        for (int k = 0; k < Hh; k += 4) {
            float w0 = W[(k+0)*Hh+h], w1 = W[(k+1)*Hh+h];
            float w2 = W[(k+2)*Hh+h], w3 = W[(k+3)*Hh+h];
            #pragma unroll
            for (int r = 0; r < RN; r++) {
                float4 x = *(const float4*)&xs[r][k];
                a[r] += x.x*w0 + x.y*w1 + x.z*w2 + x.w*w3;
            }
        }
        float* dst = kh ? g_preB : g_preA;
        #pragma unroll
        for (int r = 0; r < RN; r++) dst[(r0+r)*Hh + h] = a[r];
        for (int r = kh*2; r < kh*2+2; r++) g_agg[(r0+r)*Hh + h] = 0.f;
    } else {
        // output head
        float o[RN] = {0.f, 0.f, 0.f, 0.f};
        for (int k = kh*64; k < kh*64+64; k += 4) {
            float w0 = ow1[(k+0)*Hh+h], w1 = ow1[(k+1)*Hh+h];
            float w2 = ow1[(k+2)*Hh+h], w3 = ow1[(k+3)*Hh+h];
            #pragma unroll
            for (int r = 0; r < RN; r++) {
                float4 x = *(const float4*)&xs[r][k];
                o[r] += x.x*w0 + x.y*w1 + x.z*w2 + x.w*w3;
            }
        }
        #pragma unroll
        for (int r = 0; r < RN; r++) part[kh][r][h] = o[r];
        __syncthreads();
        if (kh == 0) {
            float ob1h = ob1[h], ow2h = ow2[h];
            #pragma unroll
            for (int r = 0; r < RN; r++) {
                float val = silu_f(part[0][r][h] + part[1][r][h] + ob1h) * ow2h;
                #pragma unroll
                for (int off = 16; off > 0; off >>= 1)
                    val += __shfl_down_sync(0xffffffffu, val, off);
                if ((h & 31) == 0) red[r][h >> 5] = val;
            }
        }
        __syncthreads();
        if (tid == 0) {
            #pragma unroll
            for (int r = 0; r < RN; r++) {
                float v = red[r][0] + red[r][1] + red[r][2] + red[r][3] + ob2[0];
                v *= mask[r0 + r];
                atomicAdd(&out[(r0 + r) / Nn], v);
            }
        }
    }
}

extern "C" void kernel_launch(void* const* d_in, const int* in_sizes, int n_in,
                              void* d_out, int out_size) {
    const int*   node_indices = (const int*)  d_in[0];
    const float* positions    = (const float*)d_in[1];
    const int*   adjacency    = (const int*)  d_in[2];
    const float* mask         = (const float*)d_in[3];
    const float* emb          = (const float*)d_in[4];
    const float* dpw          = (const float*)d_in[5];
    const float* dpb          = (const float*)d_in[6];
    const float* rbf_w1 = (const float*)d_in[7];
    const float* rbf_b1 = (const float*)d_in[8];
    const float* rbf_w2 = (const float*)d_in[9];
    const float* rbf_b2 = (const float*)d_in[10];
    const float* dir_w1 = (const float*)d_in[11];
    const float* dir_b1 = (const float*)d_in[12];
    const float* dir_w2 = (const float*)d_in[13];
    const float* dir_b2 = (const float*)d_in[14];
    const float* edge_w1 = (const float*)d_in[15];
    const float* edge_b1 = (const float*)d_in[16];
    const float* edge_w2 = (const float*)d_in[17];
    const float* edge_b2 = (const float*)d_in[18];
    const float* node_w1 = (const float*)d_in[19];
    const float* node_b1 = (const float*)d_in[20];
    const float* node_w2 = (const float*)d_in[21];
    const float* node_b2 = (const float*)d_in[22];
    const float* ow1 = (const float*)d_in[23];
    const float* ob1 = (const float*)d_in[24];
    const float* ow2 = (const float*)d_in[25];
    const float* ob2 = (const float*)d_in[26];
    float* out = (float*)d_out;

    k_init<<<ROWS/RN, 256>>>(node_indices, emb, edge_w1, out);  // resets g_nE
    k_edges<<<ROWS, Nn>>>(positions, adjacency, mask, dpw, dpb);
    k_fold<<<3*65, 256>>>(rbf_w2, rbf_b2, dir_w2, dir_b2, edge_w1, edge_b1);
    for (int t = 0; t < NBt; t++) {
        k_edge_mlp<<<GRID_E, Hh>>>(rbf_w1, rbf_b1, dir_w1, dir_b1, t);
        k_node<<<ROWS/RN, 256>>>(edge_w2, edge_b2, node_w1, node_b1, node_w2, node_b2,
                                 edge_w1, ow1, ob1, ow2, ob2, mask, out, t);
    }
}

// round 13
// speedup vs baseline: 1.6908x; 1.2010x over previous
#include <cuda_runtime.h>
#include <math.h>

#define Bq   4
#define Nn   192
#define Hh   128
#define NBt  3
#define ROWS (Bq*Nn)       // 768
#define EMAX (ROWS*Nn)
#define TE   32            // edges per tile
#define FST  12            // feature stride (floats)
#define SHS  36            // sh row stride (floats)
#define GRID_E 740
#define RN   4             // rows per CTA, node-side

typedef unsigned long long ull;

// ---- scratch (device globals) ----
__device__ __align__(16) float g_F[ROWS*Hh];
__device__ __align__(16) float g_preA[ROWS*Hh];
__device__ __align__(16) float g_preB[ROWS*Hh];
__device__ __align__(16) float g_agg[ROWS*Hh];
__device__ int   g_cnt[ROWS];
__device__ int   g_nE;
__device__ int   g_eI[EMAX];
__device__ int   g_eJ[EMAX];
__device__ __align__(16) float g_feat[(size_t)EMAX*FST];
// weight fragments for mma.m16n8k8.tf32: [t][kf=32][mf=8][hi/lo=2][lane=32][4]
__device__ __align__(16) float g_Wfrag[(size_t)NBt*32*8*2*128];
__device__ __align__(16) float g_cvec[NBt*Hh];

__device__ __forceinline__ float silu_f(float x) { return x / (1.0f + __expf(-x)); }
__device__ __forceinline__ float tf32r(float x) {
    unsigned u; asm("cvt.rna.tf32.f32 %0, %1;" : "=r"(u) : "f"(x));
    return __uint_as_float(u);
}
__device__ __forceinline__ void mma_tf32(float* c, float4 a, unsigned b0, unsigned b1) {
    asm("mma.sync.aligned.m16n8k8.row.col.f32.tf32.tf32.f32 "
        "{%0,%1,%2,%3},{%4,%5,%6,%7},{%8,%9},{%0,%1,%2,%3};"
        : "+f"(c[0]), "+f"(c[1]), "+f"(c[2]), "+f"(c[3])
        : "r"(__float_as_uint(a.x)), "r"(__float_as_uint(a.y)),
          "r"(__float_as_uint(a.z)), "r"(__float_as_uint(a.w)),
          "r"(b0), "r"(b1));
}

// write folded weight (kk,h) into hi/lo tf32 fragment layout
__device__ __forceinline__ void wfrag_store(int t, int kk, int h, float s) {
    int kf = kk >> 3, kl = kk & 7, c = kl & 3, ch = kl >> 2;
    int mf = h >> 4,  hl = h & 15, r = hl & 7, rh = hl >> 3;
    int lane = r*4 + c, i = rh + 2*ch;
    float shi = tf32r(s);
    float slo = tf32r(s - shi);
    size_t base = (((size_t)t*32 + kf)*8 + mf)*2;
    g_Wfrag[(base + 0)*128 + lane*4 + i] = shi;
    g_Wfrag[(base + 1)*128 + lane*4 + i] = slo;
}

// feats = emb[idx]; preA/preB block 0. RN=4 rows/CTA, 256 thr (kh=0:W1a, kh=1:W1b)
__global__ void k_init(const int* __restrict__ idx, const float* __restrict__ emb,
                       const float* __restrict__ ew1, float* __restrict__ out) {
    int tid = threadIdx.x;
    int h = tid & 127, kh = tid >> 7;
    int r0 = blockIdx.x * RN;
    __shared__ __align__(16) float xs[RN][Hh];
    for (int r = kh*2; r < kh*2+2; r++) {
        float v = emb[idx[r0+r]*Hh + h];
        g_F[(r0+r)*Hh + h] = v;
        xs[r][h] = v;
        g_agg[(r0+r)*Hh + h] = 0.f;
    }
    if (blockIdx.x == 0 && tid < Bq) out[tid] = 0.f;
    if (blockIdx.x == 0 && tid == 0) g_nE = 0;
    __syncthreads();
    const float* W = ew1 + (size_t)kh*Hh*Hh;
    float a[RN] = {0.f, 0.f, 0.f, 0.f};
    for (int k = 0; k < Hh; k += 4) {
        float w0 = W[(k+0)*Hh+h], w1 = W[(k+1)*Hh+h];
        float w2 = W[(k+2)*Hh+h], w3 = W[(k+3)*Hh+h];
        #pragma unroll
        for (int r = 0; r < RN; r++) {
            float4 x = *(const float4*)&xs[r][k];
            a[r] += x.x*w0 + x.y*w1 + x.z*w2 + x.w*w3;
        }
    }
    float* dst = kh ? g_preB : g_preA;
    #pragma unroll
    for (int r = 0; r < RN; r++) dst[(r0+r)*Hh + h] = a[r];
}

// flat edge list + block-invariant geometry features
__global__ void k_edges(const float* __restrict__ pos, const int* __restrict__ adj,
                        const float* __restrict__ mask,
                        const float* __restrict__ dpw, const float* __restrict__ dpb) {
    int row = blockIdx.x;
    int b = row / Nn, i = row % Nn;
    int j = threadIdx.x;
    __shared__ int s_cnt, s_base;
    if (j == 0) s_cnt = 0;
    __syncthreads();

    const float* pb = pos + (size_t)b*Nn*3;
    float xi = pb[i*3+0], yi = pb[i*3+1], zi = pb[i*3+2];
    float xj = pb[j*3+0], yj = pb[j*3+1], zj = pb[j*3+2];
    float dx = xi-xj, dy = yi-yj, dz = zi-zj;
    float dist = sqrtf(dx*dx + dy*dy + dz*dz);
    bool valid = (mask[row] > 0.f) && (mask[b*Nn + j] > 0.f) && (dist <= 5.0f)
                 && (adj[(size_t)b*Nn*Nn + (size_t)i*Nn + j] > 0) && (i != j);
    int el = -1;
    float ft[10];
    if (valid) {
        el = atomicAdd(&s_cnt, 1);
        float inv = 1.0f / (dist + 1e-8f);
        float ux = dx*inv, uy = dy*inv, uz = dz*inv;
        const float w = (5.0f/6.0f) + 1e-8f;
        #pragma unroll
        for (int r = 0; r < 6; r++) {
            float t = (dist - (float)r) / w;
            ft[r] = expf(-0.5f * t * t);
        }
        #pragma unroll
        for (int s = 0; s < 4; s++) {
            float vv = ux*dpw[0*4+s] + uy*dpw[1*4+s] + uz*dpw[2*4+s] + dpb[s];
            ft[6+s] = tanhf(vv);
        }
    }
    __syncthreads();
    if (j == 0) {
        g_cnt[row] = s_cnt;
        s_base = atomicAdd(&g_nE, s_cnt);
    }
    __syncthreads();
    if (valid) {
        int e = s_base + el;
        g_eI[e] = row;
        g_eJ[e] = b*Nn + j;
        float4* fo = (float4*)&g_feat[(size_t)e*FST];
        fo[0] = make_float4(ft[0], ft[1], ft[2], ft[3]);
        fo[1] = make_float4(ft[4], ft[5], ft[6], ft[7]);
        fo[2] = make_float4(ft[8], ft[9], 0.f, 0.f);
    }
}

// weight folding: R12 structure, output into tf32 hi/lo fragment layout
__global__ void k_fold(const float* __restrict__ rw2, const float* __restrict__ rb2,
                       const float* __restrict__ dw2, const float* __restrict__ db2,
                       const float* __restrict__ ew1, const float* __restrict__ eb1) {
    int tid = threadIdx.x;
    int h = tid & 127, kh = tid >> 7;
    int t   = blockIdx.x / 65;
    int sub = blockIdx.x % 65;
    const float* W1c = ew1 + (size_t)t*4*Hh*Hh + 2*Hh*Hh;
    const float* W1d = W1c + Hh*Hh;
    __shared__ __align__(16) float srow[RN][Hh];
    __shared__ float part[2][RN][Hh];
    if (sub < 64) {
        int kk0 = sub * RN;
        const float* W = (kk0 < 128) ? W1c : W1d;
        for (int r = kh*2; r < kh*2+2; r++) {
            int kk = kk0 + r;
            const float* src = (kk < 128) ? (rw2 + ((size_t)t*128 + kk)*Hh)
                                          : (dw2 + ((size_t)t*128 + kk - 128)*Hh);
            srow[r][h] = src[h];
        }
        __syncthreads();
        float acc[RN] = {0.f, 0.f, 0.f, 0.f};
        for (int m = kh*64; m < kh*64+64; m += 4) {
            float w0 = W[(m+0)*Hh+h], w1 = W[(m+1)*Hh+h];
            float w2 = W[(m+2)*Hh+h], w3 = W[(m+3)*Hh+h];
            #pragma unroll
            for (int r = 0; r < RN; r++) {
                float4 x = *(const float4*)&srow[r][m];
                acc[r] += x.x*w0 + x.y*w1 + x.z*w2 + x.w*w3;
            }
        }
        #pragma unroll
        for (int r = 0; r < RN; r++) part[kh][r][h] = acc[r];
        __syncthreads();
        if (kh == 0) {
            #pragma unroll
            for (int r = 0; r < RN; r++)
                wfrag_store(t, kk0 + r, h, part[0][r][h] + part[1][r][h]);
        }
    } else {
        __shared__ float rb[Hh], db[Hh];
        if (kh == 0) rb[h] = rb2[t*Hh + h];
        else         db[h] = db2[t*Hh + h];
        __syncthreads();
        float s = 0.f;
        for (int m = kh*64; m < kh*64+64; m++)
            s += rb[m]*W1c[m*Hh + h] + db[m]*W1d[m*Hh + h];
        part[kh][0][h] = s;
        __syncthreads();
        if (kh == 0) g_cvec[t*Hh + h] = eb1[t*Hh + h] + part[0][0][h] + part[1][0][h];
    }
}

// Edge MLP + aggregation: build (tf32-rounded) into sh, GEMM via mma.m16n8k8.tf32
__global__ void __launch_bounds__(Hh, 5)
k_edge_mlp(const float* __restrict__ rw1, const float* __restrict__ rb1,
           const float* __restrict__ dw1, const float* __restrict__ db1, int t) {
    __shared__ __align__(16) float sh[256*SHS];
    __shared__ int s_eI[TE], s_eJ[TE];
    int tid  = threadIdx.x;
    int lane = tid & 31;
    int w    = tid >> 5;
    int tig  = lane & 3, g = lane >> 2;

    int nE = g_nE;
    int nT = (nE + TE - 1) / TE;
    const float* WF = g_Wfrag + (size_t)t*32*8*2*128;

    for (int tile = blockIdx.x; tile < nT; tile += gridDim.x) {
        int e0 = tile * TE;
        int ne = min(TE, nE - e0);
        __syncthreads();
        if (tid < TE) {
            int idx = (tid < ne) ? (e0 + tid) : e0;
            s_eI[tid] = g_eI[idx];
            s_eJ[tid] = g_eJ[idx];
        }
        // build: thread computes k=tid (rbf) and k=tid+128 (dir), all 32 edges
        {
            float rb1h = rb1[t*Hh + tid], db1h = db1[t*Hh + tid];
            float rw[6], dwv[4];
            #pragma unroll
            for (int r = 0; r < 6; r++) rw[r] = rw1[(t*6 + r)*Hh + tid];
            #pragma unroll
            for (int r = 0; r < 4; r++) dwv[r] = dw1[(t*4 + r)*Hh + tid];
            #pragma unroll
            for (int q = 0; q < 4; q++) {
                float va[8], vb[8];
                #pragma unroll
                for (int e = 0; e < 8; e++) {
                    int ge = q*8 + e;
                    if (ge < ne) {
                        const float4* fp = (const float4*)&g_feat[(size_t)(e0+ge)*FST];
                        float4 fa = fp[0], fb4 = fp[1], fc = fp[2];
                        float a = rb1h + fa.x*rw[0] + fa.y*rw[1] + fa.z*rw[2]
                                       + fa.w*rw[3] + fb4.x*rw[4] + fb4.y*rw[5];
                        float bb = db1h + fb4.z*dwv[0] + fb4.w*dwv[1]
                                        + fc.x*dwv[2] + fc.y*dwv[3];
                        va[e] = tf32r(silu_f(a));
                        vb[e] = tf32r(silu_f(bb));
                    } else { va[e] = 0.f; vb[e] = 0.f; }
                }
                float4* rowA = (float4*)&sh[tid*SHS + q*8];
                float4* rowB = (float4*)&sh[(128+tid)*SHS + q*8];
                rowA[0] = make_float4(va[0], va[1], va[2], va[3]);
                rowA[1] = make_float4(va[4], va[5], va[6], va[7]);
                rowB[0] = make_float4(vb[0], vb[1], vb[2], vb[3]);
                rowB[1] = make_float4(vb[4], vb[5], vb[6], vb[7]);
            }
        }
        __syncthreads();

        // GEMM: D[h,e] = sum_k W[k,h] * sh[k,e]; warp w covers h in [32w, 32w+32)
        float acc[2][4][4];
        #pragma unroll
        for (int mi = 0; mi < 2; mi++)
            #pragma unroll
            for (int nf = 0; nf < 4; nf++)
                #pragma unroll
                for (int i = 0; i < 4; i++) acc[mi][nf][i] = 0.f;

        #pragma unroll 2
        for (int kf = 0; kf < 32; kf++) {
            const float* bp = &sh[(kf*8 + tig)*SHS + g];
            unsigned b0[4], b1[4];
            #pragma unroll
            for (int nf = 0; nf < 4; nf++) {
                b0[nf] = __float_as_uint(bp[nf*8]);
                b1[nf] = __float_as_uint(bp[4*SHS + nf*8]);
            }
            #pragma unroll
            for (int mi = 0; mi < 2; mi++) {
                int mf = 2*w + mi;
                const float4* af = (const float4*)(WF + (((size_t)kf*8 + mf)*2)*128);
                float4 ahi = __ldg(af + lane);
                float4 alo = __ldg(af + 32 + lane);
                #pragma unroll
                for (int nf = 0; nf < 4; nf++) mma_tf32(acc[mi][nf], ahi, b0[nf], b1[nf]);
                #pragma unroll
                for (int nf = 0; nf < 4; nf++) mma_tf32(acc[mi][nf], alo, b0[nf], b1[nf]);
            }
        }

        // epilogue: add base, silu, run-compressed atomic aggregation
        #pragma unroll
        for (int mi = 0; mi < 2; mi++) {
            #pragma unroll
            for (int ib = 0; ib < 2; ib++) {
                int h = w*32 + mi*16 + ib*8 + g;
                float cvh = g_cvec[t*Hh + h];
                int cur = -1; float ssum = 0.f;
                #pragma unroll
                for (int nf = 0; nf < 4; nf++) {
                    #pragma unroll
                    for (int eb = 0; eb < 2; eb++) {
                        int e = nf*8 + 2*tig + eb;
                        if (e < ne) {
                            int iR = s_eI[e];
                            float base = g_preA[iR*Hh + h] + g_preB[s_eJ[e]*Hh + h] + cvh;
                            float m = silu_f(acc[mi][nf][2*ib + eb] + base);
                            if (iR != cur) {
                                if (cur >= 0) atomicAdd(&g_agg[cur*Hh + h], ssum);
                                cur = iR; ssum = m;
                            } else ssum += m;
                        }
                    }
                }
                if (cur >= 0) atomicAdd(&g_agg[cur*Hh + h], ssum);
            }
        }
    }
}

// node update: RN=4 rows/CTA, 256 thr, kh splits every k-chain (R12 winner)
__global__ void k_node(const float* __restrict__ ew2, const float* __restrict__ eb2,
                       const float* __restrict__ nw1, const float* __restrict__ nb1,
                       const float* __restrict__ nw2, const float* __restrict__ nb2,
                       const float* __restrict__ ew1,
                       const float* __restrict__ ow1, const float* __restrict__ ob1,
                       const float* __restrict__ ow2, const float* __restrict__ ob2,
                       const float* __restrict__ mask, float* __restrict__ out, int t) {
    int tid = threadIdx.x;
    int h = tid & 127, kh = tid >> 7;
    int r0 = blockIdx.x * RN;
    __shared__ __align__(16) float xs[RN][256];
    __shared__ __align__(16) float aggs[RN][Hh];
    __shared__ __align__(16) float us[RN][Hh];
    __shared__ float part[2][RN][Hh];
    __shared__ float red[RN][4];

    for (int r = kh*2; r < kh*2+2; r++) {
        xs[r][h]   = g_F[(r0+r)*Hh + h];
        aggs[r][h] = g_agg[(r0+r)*Hh + h];
    }
    __syncthreads();

    const float* EW2 = ew2 + (size_t)t*Hh*Hh;
    {
        float s[RN] = {0.f, 0.f, 0.f, 0.f};
        for (int k = kh*64; k < kh*64+64; k += 4) {
            float w0 = EW2[(k+0)*Hh+h], w1 = EW2[(k+1)*Hh+h];
            float w2 = EW2[(k+2)*Hh+h], w3 = EW2[(k+3)*Hh+h];
            #pragma unroll
            for (int r = 0; r < RN; r++) {
                float4 a = *(const float4*)&aggs[r][k];
                s[r] += a.x*w0 + a.y*w1 + a.z*w2 + a.w*w3;
            }
        }
        #pragma unroll
        for (int r = 0; r < RN; r++) part[kh][r][h] = s[r];
    }
    __syncthreads();
    if (kh == 0) {
        float e2 = eb2[t*Hh + h];
        #pragma unroll
        for (int r = 0; r < RN; r++)
            xs[r][Hh + h] = part[0][r][h] + part[1][r][h] + (float)g_cnt[r0+r] * e2;
    }
    __syncthreads();

    const float* NW1 = nw1 + (size_t)t*256*Hh;
    {
        float u[RN] = {0.f, 0.f, 0.f, 0.f};
        for (int k = kh*128; k < kh*128+128; k += 4) {
            float w0 = NW1[(k+0)*Hh+h], w1 = NW1[(k+1)*Hh+h];
            float w2 = NW1[(k+2)*Hh+h], w3 = NW1[(k+3)*Hh+h];
            #pragma unroll
            for (int r = 0; r < RN; r++) {
                float4 x = *(const float4*)&xs[r][k];
                u[r] += x.x*w0 + x.y*w1 + x.z*w2 + x.w*w3;
            }
        }
        #pragma unroll
        for (int r = 0; r < RN; r++) part[kh][r][h] = u[r];
    }
    __syncthreads();
    if (kh == 0) {
        float b1 = nb1[t*Hh + h];
        #pragma unroll
        for (int r = 0; r < RN; r++)
            us[r][h] = silu_f(part[0][r][h] + part[1][r][h] + b1);
    }
    __syncthreads();

    const float* NW2 = nw2 + (size_t)t*Hh*Hh;
    {
        float upd[RN] = {0.f, 0.f, 0.f, 0.f};
        for (int k = kh*64; k < kh*64+64; k += 4) {
            float w0 = NW2[(k+0)*Hh+h], w1 = NW2[(k+1)*Hh+h];
            float w2 = NW2[(k+2)*Hh+h], w3 = NW2[(k+3)*Hh+h];
            #pragma unroll
            for (int r = 0; r < RN; r++) {
                float4 x = *(const float4*)&us[r][k];
                upd[r] += x.x*w0 + x.y*w1 + x.z*w2 + x.w*w3;
            }
        }
        #pragma unroll
        for (int r = 0; r < RN; r++) part[kh][r][h] = upd[r];
    }
    __syncthreads();
    if (kh == 0) {
        float b2v = nb2[t*Hh + h];
        #pragma unroll
        for (int r = 0; r < RN; r++) {
            float newf = xs[r][h] + part[0][r][h] + part[1][r][h] + b2v;
            g_F[(r0+r)*Hh + h] = newf;
            xs[r][h] = newf;
        }
    }
    __syncthreads();

    if (t + 1 < NBt) {
        const float* W = ew1 + (size_t)(t+1)*4*Hh*Hh + (size_t)kh*Hh*Hh;
        float a[RN] = {0.f, 0.f, 0.f, 0.f};
        for (int k = 0; k < Hh; k += 4) {
            float w0 = W[(k+0)*Hh+h], w1 = W[(k+1)*Hh+h];
            float w2 = W[(k+2)*Hh+h], w3 = W[(k+3)*Hh+h];
            #pragma unroll
            for (int r = 0; r < RN; r++) {
                float4 x = *(const float4*)&xs[r][k];
                a[r] += x.x*w0 + x.y*w1 + x.z*w2 + x.w*w3;
            }
        }
        float* dst = kh ? g_preB : g_preA;
        #pragma unroll
        for (int r = 0; r < RN; r++) dst[(r0+r)*Hh + h] = a[r];
        for (int r = kh*2; r < kh*2+2; r++) g_agg[(r0+r)*Hh + h] = 0.f;
    } else {
        float o[RN] = {0.f, 0.f, 0.f, 0.f};
        for (int k = kh*64; k < kh*64+64; k += 4) {
            float w0 = ow1[(k+0)*Hh+h], w1 = ow1[(k+1)*Hh+h];
            float w2 = ow1[(k+2)*Hh+h], w3 = ow1[(k+3)*Hh+h];
            #pragma unroll
            for (int r = 0; r < RN; r++) {
                float4 x = *(const float4*)&xs[r][k];
                o[r] += x.x*w0 + x.y*w1 + x.z*w2 + x.w*w3;
            }
        }
        #pragma unroll
        for (int r = 0; r < RN; r++) part[kh][r][h] = o[r];
        __syncthreads();
        if (kh == 0) {
            float ob1h = ob1[h], ow2h = ow2[h];
            #pragma unroll
            for (int r = 0; r < RN; r++) {
                float val = silu_f(part[0][r][h] + part[1][r][h] + ob1h) * ow2h;
                #pragma unroll
                for (int off = 16; off > 0; off >>= 1)
                    val += __shfl_down_sync(0xffffffffu, val, off);
                if ((h & 31) == 0) red[r][h >> 5] = val;
            }
        }
        __syncthreads();
        if (tid == 0) {
            #pragma unroll
            for (int r = 0; r < RN; r++) {
                float v = red[r][0] + red[r][1] + red[r][2] + red[r][3] + ob2[0];
                v *= mask[r0 + r];
                atomicAdd(&out[(r0 + r) / Nn], v);
            }
        }
    }
}

extern "C" void kernel_launch(void* const* d_in, const int* in_sizes, int n_in,
                              void* d_out, int out_size) {
    const int*   node_indices = (const int*)  d_in[0];
    const float* positions    = (const float*)d_in[1];
    const int*   adjacency    = (const int*)  d_in[2];
    const float* mask         = (const float*)d_in[3];
    const float* emb          = (const float*)d_in[4];
    const float* dpw          = (const float*)d_in[5];
    const float* dpb          = (const float*)d_in[6];
    const float* rbf_w1 = (const float*)d_in[7];
    const float* rbf_b1 = (const float*)d_in[8];
    const float* rbf_w2 = (const float*)d_in[9];
    const float* rbf_b2 = (const float*)d_in[10];
    const float* dir_w1 = (const float*)d_in[11];
    const float* dir_b1 = (const float*)d_in[12];
    const float* dir_w2 = (const float*)d_in[13];
    const float* dir_b2 = (const float*)d_in[14];
    const float* edge_w1 = (const float*)d_in[15];
    const float* edge_b1 = (const float*)d_in[16];
    const float* edge_w2 = (const float*)d_in[17];
    const float* edge_b2 = (const float*)d_in[18];
    const float* node_w1 = (const float*)d_in[19];
    const float* node_b1 = (const float*)d_in[20];
    const float* node_w2 = (const float*)d_in[21];
    const float* node_b2 = (const float*)d_in[22];
    const float* ow1 = (const float*)d_in[23];
    const float* ob1 = (const float*)d_in[24];
    const float* ow2 = (const float*)d_in[25];
    const float* ob2 = (const float*)d_in[26];
    float* out = (float*)d_out;

    k_init<<<ROWS/RN, 256>>>(node_indices, emb, edge_w1, out);  // resets g_nE
    k_edges<<<ROWS, Nn>>>(positions, adjacency, mask, dpw, dpb);
    k_fold<<<3*65, 256>>>(rbf_w2, rbf_b2, dir_w2, dir_b2, edge_w1, edge_b1);
    for (int t = 0; t < NBt; t++) {
        k_edge_mlp<<<GRID_E, Hh>>>(rbf_w1, rbf_b1, dir_w1, dir_b1, t);
        k_node<<<ROWS/RN, 256>>>(edge_w2, edge_b2, node_w1, node_b1, node_w2, node_b2,
                                 edge_w1, ow1, ob1, ow2, ob2, mask, out, t);
    }
}

// round 15
// speedup vs baseline: 1.9051x; 1.1268x over previous
#include <cuda_runtime.h>
#include <math.h>

#define Bq   4
#define Nn   192
#define Hh   128
#define NBt  3
#define ROWS (Bq*Nn)       // 768
#define EMAX (ROWS*Nn)
#define TE   32            // edges per tile
#define FST  12            // feature stride (floats)
#define SHS  40            // sh row stride (floats): conflict-free B-frag loads
#define GRID_E 740
#define RN   4             // rows per CTA, node-side

typedef unsigned long long ull;

// ---- scratch (device globals) ----
__device__ __align__(16) float g_F[ROWS*Hh];
__device__ __align__(16) float g_preA[ROWS*Hh];
__device__ __align__(16) float g_preB[ROWS*Hh];
__device__ __align__(16) float g_agg[ROWS*Hh];
__device__ int   g_cnt[ROWS];
__device__ int   g_nE;       // static-zero initially; reset by last edge launch
__device__ int   g_done;
__device__ int   g_eI[EMAX];
__device__ int   g_eJ[EMAX];
__device__ __align__(16) float g_feat[(size_t)EMAX*FST];
// weight fragments for mma.m16n8k8.tf32 (hi only): [t][kf=32][mf=8][lane*4+i]
__device__ __align__(16) float g_Wfrag[(size_t)NBt*32*8*128];
__device__ __align__(16) float g_cvec[NBt*Hh];

__device__ __forceinline__ float silu_f(float x) { return x / (1.0f + __expf(-x)); }
__device__ __forceinline__ float tf32r(float x) {
    unsigned u; asm("cvt.rna.tf32.f32 %0, %1;" : "=r"(u) : "f"(x));
    return __uint_as_float(u);
}
__device__ __forceinline__ void mma_tf32(float* c, float4 a, unsigned b0, unsigned b1) {
    asm("mma.sync.aligned.m16n8k8.row.col.f32.tf32.tf32.f32 "
        "{%0,%1,%2,%3},{%4,%5,%6,%7},{%8,%9},{%0,%1,%2,%3};"
        : "+f"(c[0]), "+f"(c[1]), "+f"(c[2]), "+f"(c[3])
        : "r"(__float_as_uint(a.x)), "r"(__float_as_uint(a.y)),
          "r"(__float_as_uint(a.z)), "r"(__float_as_uint(a.w)),
          "r"(b0), "r"(b1));
}

// write folded weight (kk,h) into tf32 A-fragment layout
__device__ __forceinline__ void wfrag_store(int t, int kk, int h, float s) {
    int kf = kk >> 3, kl = kk & 7, c = kl & 3, ch = kl >> 2;
    int mf = h >> 4,  hl = h & 15, r = hl & 7, rh = hl >> 3;
    int lane = r*4 + c, i = rh + 2*ch;
    g_Wfrag[(((size_t)t*32 + kf)*8 + mf)*128 + lane*4 + i] = tf32r(s);
}

// ===== fused prologue: init (192 CTAs) | edges (768) | fold (195) =====
__global__ void k_pre(const int* __restrict__ idx, const float* __restrict__ emb,
                      const float* __restrict__ ew1, float* __restrict__ out,
                      const float* __restrict__ pos, const int* __restrict__ adj,
                      const float* __restrict__ mask,
                      const float* __restrict__ dpw, const float* __restrict__ dpb,
                      const float* __restrict__ rw2, const float* __restrict__ rb2,
                      const float* __restrict__ dw2, const float* __restrict__ db2,
                      const float* __restrict__ eb1) {
    int bid = blockIdx.x;
    int tid = threadIdx.x;

    if (bid < 192) {
        // ---- init role: feats, preA/preB block 0, zero agg/out ----
        int h = tid & 127, kh = tid >> 7;
        int r0 = bid * RN;
        __shared__ __align__(16) float xs[RN][Hh];
        for (int r = kh*2; r < kh*2+2; r++) {
            float v = emb[idx[r0+r]*Hh + h];
            g_F[(r0+r)*Hh + h] = v;
            xs[r][h] = v;
            g_agg[(r0+r)*Hh + h] = 0.f;
        }
        if (bid == 0 && tid < Bq) out[tid] = 0.f;
        __syncthreads();
        const float* W = ew1 + (size_t)kh*Hh*Hh;
        float a[RN] = {0.f, 0.f, 0.f, 0.f};
        for (int k = 0; k < Hh; k += 4) {
            float w0 = W[(k+0)*Hh+h], w1 = W[(k+1)*Hh+h];
            float w2 = W[(k+2)*Hh+h], w3 = W[(k+3)*Hh+h];
            #pragma unroll
            for (int r = 0; r < RN; r++) {
                float4 x = *(const float4*)&xs[r][k];
                a[r] += x.x*w0 + x.y*w1 + x.z*w2 + x.w*w3;
            }
        }
        float* dst = kh ? g_preB : g_preA;
        #pragma unroll
        for (int r = 0; r < RN; r++) dst[(r0+r)*Hh + h] = a[r];
    } else if (bid < 960) {
        // ---- edges role: flat edge list + geometry features ----
        int row = bid - 192;
        int b = row / Nn, i = row % Nn;
        int j = tid;
        bool act = j < Nn;
        __shared__ int s_cnt, s_base;
        if (tid == 0) s_cnt = 0;
        __syncthreads();

        bool valid = false;
        int el = -1;
        float ft[10];
        if (act) {
            const float* pb = pos + (size_t)b*Nn*3;
            float xi = pb[i*3+0], yi = pb[i*3+1], zi = pb[i*3+2];
            float xj = pb[j*3+0], yj = pb[j*3+1], zj = pb[j*3+2];
            float dx = xi-xj, dy = yi-yj, dz = zi-zj;
            float dist = sqrtf(dx*dx + dy*dy + dz*dz);
            valid = (mask[row] > 0.f) && (mask[b*Nn + j] > 0.f) && (dist <= 5.0f)
                    && (adj[(size_t)b*Nn*Nn + (size_t)i*Nn + j] > 0) && (i != j);
            if (valid) {
                el = atomicAdd(&s_cnt, 1);
                float inv = 1.0f / (dist + 1e-8f);
                float ux = dx*inv, uy = dy*inv, uz = dz*inv;
                const float w = (5.0f/6.0f) + 1e-8f;
                #pragma unroll
                for (int r = 0; r < 6; r++) {
                    float tt = (dist - (float)r) / w;
                    ft[r] = expf(-0.5f * tt * tt);
                }
                #pragma unroll
                for (int s = 0; s < 4; s++) {
                    float vv = ux*dpw[0*4+s] + uy*dpw[1*4+s] + uz*dpw[2*4+s] + dpb[s];
                    ft[6+s] = tanhf(vv);
                }
            }
        }
        __syncthreads();
        if (tid == 0) {
            g_cnt[row] = s_cnt;
            s_base = atomicAdd(&g_nE, s_cnt);
        }
        __syncthreads();
        if (valid) {
            int e = s_base + el;
            g_eI[e] = row;
            g_eJ[e] = b*Nn + j;
            float4* fo = (float4*)&g_feat[(size_t)e*FST];
            fo[0] = make_float4(ft[0], ft[1], ft[2], ft[3]);
            fo[1] = make_float4(ft[4], ft[5], ft[6], ft[7]);
            fo[2] = make_float4(ft[8], ft[9], 0.f, 0.f);
        }
    } else {
        // ---- fold role: folded weights -> tf32 fragments; cvec ----
        int fb = bid - 960;
        int h = tid & 127, kh = tid >> 7;
        int t   = fb / 65;
        int sub = fb % 65;
        const float* W1c = ew1 + (size_t)t*4*Hh*Hh + 2*Hh*Hh;
        const float* W1d = W1c + Hh*Hh;
        __shared__ __align__(16) float srow[RN][Hh];
        __shared__ float part[2][RN][Hh];
        if (sub < 64) {
            int kk0 = sub * RN;
            const float* W = (kk0 < 128) ? W1c : W1d;
            for (int r = kh*2; r < kh*2+2; r++) {
                int kk = kk0 + r;
                const float* src = (kk < 128) ? (rw2 + ((size_t)t*128 + kk)*Hh)
                                              : (dw2 + ((size_t)t*128 + kk - 128)*Hh);
                srow[r][h] = src[h];
            }
            __syncthreads();
            float acc[RN] = {0.f, 0.f, 0.f, 0.f};
            for (int m = kh*64; m < kh*64+64; m += 4) {
                float w0 = W[(m+0)*Hh+h], w1 = W[(m+1)*Hh+h];
                float w2 = W[(m+2)*Hh+h], w3 = W[(m+3)*Hh+h];
                #pragma unroll
                for (int r = 0; r < RN; r++) {
                    float4 x = *(const float4*)&srow[r][m];
                    acc[r] += x.x*w0 + x.y*w1 + x.z*w2 + x.w*w3;
                }
            }
            #pragma unroll
            for (int r = 0; r < RN; r++) part[kh][r][h] = acc[r];
            __syncthreads();
            if (kh == 0) {
                #pragma unroll
                for (int r = 0; r < RN; r++)
                    wfrag_store(t, kk0 + r, h, part[0][r][h] + part[1][r][h]);
            }
        } else {
            __shared__ float rb[Hh], db[Hh];
            if (kh == 0) rb[h] = rb2[t*Hh + h];
            else         db[h] = db2[t*Hh + h];
            __syncthreads();
            float s = 0.f;
            for (int m = kh*64; m < kh*64+64; m++)
                s += rb[m]*W1c[m*Hh + h] + db[m]*W1d[m*Hh + h];
            part[kh][0][h] = s;
            __syncthreads();
            if (kh == 0) g_cvec[t*Hh + h] = eb1[t*Hh + h] + part[0][0][h] + part[1][0][h];
        }
    }
}

// Edge MLP + aggregation: interleaved-col smem, single-pass tf32 mma
__global__ void __launch_bounds__(Hh, 5)
k_edge_mlp(const float* __restrict__ rw1, const float* __restrict__ rb1,
           const float* __restrict__ dw1, const float* __restrict__ db1,
           int t, int doReset) {
    __shared__ __align__(16) float sh[256*SHS];
    __shared__ int s_eI[TE], s_eJ[TE];
    int tid  = threadIdx.x;
    int lane = tid & 31;
    int w    = tid >> 5;
    int tig  = lane & 3, g = lane >> 2;

    int nE = g_nE;
    int nT = (nE + TE - 1) / TE;
    const float* WF = g_Wfrag + (size_t)t*32*8*128;

    for (int tile = blockIdx.x; tile < nT; tile += gridDim.x) {
        int e0 = tile * TE;
        int ne = min(TE, nE - e0);
        __syncthreads();
        if (tid < TE) {
            int idx = (tid < ne) ? (e0 + tid) : e0;
            s_eI[tid] = g_eI[idx];
            s_eJ[tid] = g_eJ[idx];
        }
        // build: k-row tid (rbf) and 128+tid (dir); edge e stored at col (e&7)*4+(e>>3)
        {
            float rb1h = rb1[t*Hh + tid], db1h = db1[t*Hh + tid];
            float rw[6], dwv[4];
            #pragma unroll
            for (int r = 0; r < 6; r++) rw[r] = rw1[(t*6 + r)*Hh + tid];
            #pragma unroll
            for (int r = 0; r < 4; r++) dwv[r] = dw1[(t*4 + r)*Hh + tid];
            #pragma unroll
            for (int m = 0; m < 8; m++) {
                float va[4], vb[4];
                #pragma unroll
                for (int q = 0; q < 4; q++) {
                    int ge = q*8 + m;
                    if (ge < ne) {
                        const float4* fp = (const float4*)&g_feat[(size_t)(e0+ge)*FST];
                        float4 fa = fp[0], fb4 = fp[1], fc = fp[2];
                        float a = rb1h + fa.x*rw[0] + fa.y*rw[1] + fa.z*rw[2]
                                       + fa.w*rw[3] + fb4.x*rw[4] + fb4.y*rw[5];
                        float bb = db1h + fb4.z*dwv[0] + fb4.w*dwv[1]
                                        + fc.x*dwv[2] + fc.y*dwv[3];
                        va[q] = tf32r(silu_f(a));
                        vb[q] = tf32r(silu_f(bb));
                    } else { va[q] = 0.f; vb[q] = 0.f; }
                }
                *(float4*)&sh[tid*SHS + 4*m]       = make_float4(va[0], va[1], va[2], va[3]);
                *(float4*)&sh[(128+tid)*SHS + 4*m] = make_float4(vb[0], vb[1], vb[2], vb[3]);
            }
        }
        __syncthreads();

        // GEMM: D[h,e] = sum_k W[k,h]*S[k,e]; warp w: h in [32w,32w+32)
        float acc[2][4][4];
        #pragma unroll
        for (int mi = 0; mi < 2; mi++)
            #pragma unroll
            for (int nf = 0; nf < 4; nf++)
                #pragma unroll
                for (int i = 0; i < 4; i++) acc[mi][nf][i] = 0.f;

        #pragma unroll 4
        for (int kf = 0; kf < 32; kf++) {
            const float* bp = &sh[(kf*8 + tig)*SHS + 4*g];
            float4 v0 = *(const float4*)bp;
            float4 v1 = *(const float4*)(bp + 4*SHS);
            unsigned b0[4] = {__float_as_uint(v0.x), __float_as_uint(v0.y),
                              __float_as_uint(v0.z), __float_as_uint(v0.w)};
            unsigned b1[4] = {__float_as_uint(v1.x), __float_as_uint(v1.y),
                              __float_as_uint(v1.z), __float_as_uint(v1.w)};
            #pragma unroll
            for (int mi = 0; mi < 2; mi++) {
                const float4* af = (const float4*)(WF + ((size_t)kf*8 + 2*w + mi)*128);
                float4 a = __ldg(af + lane);
                #pragma unroll
                for (int nf = 0; nf < 4; nf++) mma_tf32(acc[mi][nf], a, b0[nf], b1[nf]);
            }
        }

        // epilogue: add base, silu, run-compressed atomic aggregation
        #pragma unroll
        for (int mi = 0; mi < 2; mi++) {
            #pragma unroll
            for (int ib = 0; ib < 2; ib++) {
                int h = w*32 + mi*16 + ib*8 + g;
                float cvh = g_cvec[t*Hh + h];
                int cur = -1; float ssum = 0.f;
                #pragma unroll
                for (int nf = 0; nf < 4; nf++) {
                    #pragma unroll
                    for (int eb = 0; eb < 2; eb++) {
                        int e = nf*8 + 2*tig + eb;
                        if (e < ne) {
                            int iR = s_eI[e];
                            float base = g_preA[iR*Hh + h] + g_preB[s_eJ[e]*Hh + h] + cvh;
                            float m = silu_f(acc[mi][nf][2*ib + eb] + base);
                            if (iR != cur) {
                                if (cur >= 0) atomicAdd(&g_agg[cur*Hh + h], ssum);
                                cur = iR; ssum = m;
                            } else ssum += m;
                        }
                    }
                }
                if (cur >= 0) atomicAdd(&g_agg[cur*Hh + h], ssum);
            }
        }
    }

    // last launch: last-finishing CTA resets g_nE for the next graph replay
    if (doReset) {
        __syncthreads();
        if (tid == 0) {
            __threadfence();
            int old = atomicAdd(&g_done, 1);
            if (old == (int)gridDim.x - 1) {
                g_nE = 0;
                g_done = 0;
                __threadfence();
            }
        }
    }
}

// node update: RN=4 rows/CTA, 256 thr, kh splits every k-chain (R12 winner)
__global__ void k_node(const float* __restrict__ ew2, const float* __restrict__ eb2,
                       const float* __restrict__ nw1, const float* __restrict__ nb1,
                       const float* __restrict__ nw2, const float* __restrict__ nb2,
                       const float* __restrict__ ew1,
                       const float* __restrict__ ow1, const float* __restrict__ ob1,
                       const float* __restrict__ ow2, const float* __restrict__ ob2,
                       const float* __restrict__ mask, float* __restrict__ out, int t) {
    int tid = threadIdx.x;
    int h = tid & 127, kh = tid >> 7;
    int r0 = blockIdx.x * RN;
    __shared__ __align__(16) float xs[RN][256];
    __shared__ __align__(16) float aggs[RN][Hh];
    __shared__ __align__(16) float us[RN][Hh];
    __shared__ float part[2][RN][Hh];
    __shared__ float red[RN][4];

    for (int r = kh*2; r < kh*2+2; r++) {
        xs[r][h]   = g_F[(r0+r)*Hh + h];
        aggs[r][h] = g_agg[(r0+r)*Hh + h];
    }
    __syncthreads();

    const float* EW2 = ew2 + (size_t)t*Hh*Hh;
    {
        float s[RN] = {0.f, 0.f, 0.f, 0.f};
        for (int k = kh*64; k < kh*64+64; k += 4) {
            float w0 = EW2[(k+0)*Hh+h], w1 = EW2[(k+1)*Hh+h];
            float w2 = EW2[(k+2)*Hh+h], w3 = EW2[(k+3)*Hh+h];
            #pragma unroll
            for (int r = 0; r < RN; r++) {
                float4 a = *(const float4*)&aggs[r][k];
                s[r] += a.x*w0 + a.y*w1 + a.z*w2 + a.w*w3;
            }
        }
        #pragma unroll
        for (int r = 0; r < RN; r++) part[kh][r][h] = s[r];
    }
    __syncthreads();
    if (kh == 0) {
        float e2 = eb2[t*Hh + h];
        #pragma unroll
        for (int r = 0; r < RN; r++)
            xs[r][Hh + h] = part[0][r][h] + part[1][r][h] + (float)g_cnt[r0+r] * e2;
    }
    __syncthreads();

    const float* NW1 = nw1 + (size_t)t*256*Hh;
    {
        float u[RN] = {0.f, 0.f, 0.f, 0.f};
        for (int k = kh*128; k < kh*128+128; k += 4) {
            float w0 = NW1[(k+0)*Hh+h], w1 = NW1[(k+1)*Hh+h];
            float w2 = NW1[(k+2)*Hh+h], w3 = NW1[(k+3)*Hh+h];
            #pragma unroll
            for (int r = 0; r < RN; r++) {
                float4 x = *(const float4*)&xs[r][k];
                u[r] += x.x*w0 + x.y*w1 + x.z*w2 + x.w*w3;
            }
        }
        #pragma unroll
        for (int r = 0; r < RN; r++) part[kh][r][h] = u[r];
    }
    __syncthreads();
    if (kh == 0) {
        float b1 = nb1[t*Hh + h];
        #pragma unroll
        for (int r = 0; r < RN; r++)
            us[r][h] = silu_f(part[0][r][h] + part[1][r][h] + b1);
    }
    __syncthreads();

    const float* NW2 = nw2 + (size_t)t*Hh*Hh;
    {
        float upd[RN] = {0.f, 0.f, 0.f, 0.f};
        for (int k = kh*64; k < kh*64+64; k += 4) {
            float w0 = NW2[(k+0)*Hh+h], w1 = NW2[(k+1)*Hh+h];
            float w2 = NW2[(k+2)*Hh+h], w3 = NW2[(k+3)*Hh+h];
            #pragma unroll
            for (int r = 0; r < RN; r++) {
                float4 x = *(const float4*)&us[r][k];
                upd[r] += x.x*w0 + x.y*w1 + x.z*w2 + x.w*w3;
            }
        }
        #pragma unroll
        for (int r = 0; r < RN; r++) part[kh][r][h] = upd[r];
    }
    __syncthreads();
    if (kh == 0) {
        float b2v = nb2[t*Hh + h];
        #pragma unroll
        for (int r = 0; r < RN; r++) {
            float newf = xs[r][h] + part[0][r][h] + part[1][r][h] + b2v;
            g_F[(r0+r)*Hh + h] = newf;
            xs[r][h] = newf;
        }
    }
    __syncthreads();

    if (t + 1 < NBt) {
        const float* W = ew1 + (size_t)(t+1)*4*Hh*Hh + (size_t)kh*Hh*Hh;
        float a[RN] = {0.f, 0.f, 0.f, 0.f};
        for (int k = 0; k < Hh; k += 4) {
            float w0 = W[(k+0)*Hh+h], w1 = W[(k+1)*Hh+h];
            float w2 = W[(k+2)*Hh+h], w3 = W[(k+3)*Hh+h];
            #pragma unroll
            for (int r = 0; r < RN; r++) {
                float4 x = *(const float4*)&xs[r][k];
                a[r] += x.x*w0 + x.y*w1 + x.z*w2 + x.w*w3;
            }
        }
        float* dst = kh ? g_preB : g_preA;
        #pragma unroll
        for (int r = 0; r < RN; r++) dst[(r0+r)*Hh + h] = a[r];
        for (int r = kh*2; r < kh*2+2; r++) g_agg[(r0+r)*Hh + h] = 0.f;
    } else {
        float o[RN] = {0.f, 0.f, 0.f, 0.f};
        for (int k = kh*64; k < kh*64+64; k += 4) {
            float w0 = ow1[(k+0)*Hh+h], w1 = ow1[(k+1)*Hh+h];
            float w2 = ow1[(k+2)*Hh+h], w3 = ow1[(k+3)*Hh+h];
            #pragma unroll
            for (int r = 0; r < RN; r++) {
                float4 x = *(const float4*)&xs[r][k];
                o[r] += x.x*w0 + x.y*w1 + x.z*w2 + x.w*w3;
            }
        }
        #pragma unroll
        for (int r = 0; r < RN; r++) part[kh][r][h] = o[r];
        __syncthreads();
        if (kh == 0) {
            float ob1h = ob1[h], ow2h = ow2[h];
            #pragma unroll
            for (int r = 0; r < RN; r++) {
                float val = silu_f(part[0][r][h] + part[1][r][h] + ob1h) * ow2h;
                #pragma unroll
                for (int off = 16; off > 0; off >>= 1)
                    val += __shfl_down_sync(0xffffffffu, val, off);
                if ((h & 31) == 0) red[r][h >> 5] = val;
            }
        }
        __syncthreads();
        if (tid == 0) {
            #pragma unroll
            for (int r = 0; r < RN; r++) {
                float v = red[r][0] + red[r][1] + red[r][2] + red[r][3] + ob2[0];
                v *= mask[r0 + r];
                atomicAdd(&out[(r0 + r) / Nn], v);
            }
        }
    }
}

extern "C" void kernel_launch(void* const* d_in, const int* in_sizes, int n_in,
                              void* d_out, int out_size) {
    const int*   node_indices = (const int*)  d_in[0];
    const float* positions    = (const float*)d_in[1];
    const int*   adjacency    = (const int*)  d_in[2];
    const float* mask         = (const float*)d_in[3];
    const float* emb          = (const float*)d_in[4];
    const float* dpw          = (const float*)d_in[5];
    const float* dpb          = (const float*)d_in[6];
    const float* rbf_w1 = (const float*)d_in[7];
    const float* rbf_b1 = (const float*)d_in[8];
    const float* rbf_w2 = (const float*)d_in[9];
    const float* rbf_b2 = (const float*)d_in[10];
    const float* dir_w1 = (const float*)d_in[11];
    const float* dir_b1 = (const float*)d_in[12];
    const float* dir_w2 = (const float*)d_in[13];
    const float* dir_b2 = (const float*)d_in[14];
    const float* edge_w1 = (const float*)d_in[15];
    const float* edge_b1 = (const float*)d_in[16];
    const float* edge_w2 = (const float*)d_in[17];
    const float* edge_b2 = (const float*)d_in[18];
    const float* node_w1 = (const float*)d_in[19];
    const float* node_b1 = (const float*)d_in[20];
    const float* node_w2 = (const float*)d_in[21];
    const float* node_b2 = (const float*)d_in[22];
    const float* ow1 = (const float*)d_in[23];
    const float* ob1 = (const float*)d_in[24];
    const float* ow2 = (const float*)d_in[25];
    const float* ob2 = (const float*)d_in[26];
    float* out = (float*)d_out;

    k_pre<<<192 + ROWS + 3*65, 256>>>(node_indices, emb, edge_w1, out,
                                      positions, adjacency, mask, dpw, dpb,
                                      rbf_w2, rbf_b2, dir_w2, dir_b2, edge_b1);
    for (int t = 0; t < NBt; t++) {
        k_edge_mlp<<<GRID_E, Hh>>>(rbf_w1, rbf_b1, dir_w1, dir_b1, t, (t == NBt-1) ? 1 : 0);
        k_node<<<ROWS/RN, 256>>>(edge_w2, edge_b2, node_w1, node_b1, node_w2, node_b2,
                                 edge_w1, ow1, ob1, ow2, ob2, mask, out, t);
    }
}